// round 13
// baseline (speedup 1.0000x reference)
#include <cuda_runtime.h>
#include <math.h>
#include <stdint.h>

#define B_TOK 16384
#define D_IN  1024
#define H_DIM 512
#define O_DIM 256
#define E_NUM 8

// ---------------------------------------------------------------------------
// Scratch (__device__ globals; no allocation allowed)
// ---------------------------------------------------------------------------
__device__ float g_xr[(size_t)B_TOK * D_IN];            // x, tf32-rounded
__device__ float g_gw1t[256 * 1024];                    // [n][k]
__device__ float g_gw2t[128 * 256];
__device__ float g_w1cat[(size_t)E_NUM * 512 * 1024];   // [e*512+h][d]
__device__ float g_w2t[(size_t)E_NUM * 512 * 512];      // per-e [h_out][h_in]
__device__ float g_w3cat[(size_t)256 * 4096];           // [o][e*512+h]
__device__ float g_g1[(size_t)B_TOK * 256];
__device__ float g_g2[(size_t)B_TOK * 128];
__device__ float g_gates[(size_t)B_TOK * 8];
__device__ float g_h1s[(size_t)B_TOK * 4096];
__device__ float g_h2s[(size_t)B_TOK * 4096];

// ---------------------------------------------------------------------------
// Helpers
// ---------------------------------------------------------------------------
__device__ __forceinline__ float tf32r(float x) {
    float y;
    asm("cvt.rna.tf32.f32 %0, %1;" : "=f"(y) : "f"(x));
    return y;
}
__device__ __forceinline__ void cpa16(uint32_t d, const void* s) {
    asm volatile("cp.async.cg.shared.global [%0], [%1], 16;" :: "r"(d), "l"(s));
}
// Same as cpa16 but destination +16384 (B tile), folded as PTX immediate.
__device__ __forceinline__ void cpa16b(uint32_t d, const void* s) {
    asm volatile("cp.async.cg.shared.global [%0+16384], [%1], 16;" :: "r"(d), "l"(s));
}
// LDS.128 with compile-time immediate offset (stage/tile/fragment offsets).
template <int IMM>
__device__ __forceinline__ uint4 lds128(uint32_t addr) {
    uint4 v;
    asm volatile("ld.shared.v4.u32 {%0,%1,%2,%3}, [%4+%5];"
                 : "=r"(v.x), "=r"(v.y), "=r"(v.z), "=r"(v.w)
                 : "r"(addr), "n"(IMM));
    return v;
}
// Per-row 16B-chunk permutation: bijective on low-3 row bits; rows r and r+1
// differ in bit2 so adjacent rows in one LDS.128 phase hit disjoint bank
// groups. KEY: fperm(r+8) == fperm(r), so fragment addresses for all mi/h/nj
// row-steps (multiples of 8) share one register + compile-time immediates.
__device__ __forceinline__ uint32_t fperm(uint32_t r) {
    return ((r & 1u) << 2) | ((r >> 1) & 3u);
}

#define MMA8(c, a0, a1, a2, a3, b0, b1)                                         \
    asm volatile(                                                               \
        "mma.sync.aligned.m16n8k8.row.col.f32.tf32.tf32.f32 "                   \
        "{%0,%1,%2,%3}, {%4,%5,%6,%7}, {%8,%9}, {%0,%1,%2,%3};"                 \
        : "+f"((c)[0]), "+f"((c)[1]), "+f"((c)[2]), "+f"((c)[3])                \
        : "r"(a0), "r"(a1), "r"(a2), "r"(a3), "r"(b0), "r"(b1))

// One 32-k chunk of MMAs for stage S. All LDS addresses = 4 base registers
// + compile-time immediates; zero per-chunk address arithmetic.
// B fragments processed in two quarter-buffers of 4 (zero extra scalar work
// with immediate addressing) to cap peak live registers: acc(64) + af(16)
// + bf(16) + bases(~14) < 128-reg clamp -> no main-loop spills.
template <int S>
__device__ __forceinline__ void chunk_mma(float acc[2][8][4],
                                          uint32_t aoff0, uint32_t aoff1,
                                          uint32_t boff0, uint32_t boff1)
{
#pragma unroll
    for (int p = 0; p < 2; p++) {
        const uint32_t ao = p ? aoff1 : aoff0;
        const uint32_t bo = p ? boff1 : boff0;
        uint4 af[2][2];
        af[0][0] = lds128<S * 32768 + 0 * 2048 + 0 * 1024>(ao);
        af[0][1] = lds128<S * 32768 + 0 * 2048 + 1 * 1024>(ao);
        af[1][0] = lds128<S * 32768 + 1 * 2048 + 0 * 1024>(ao);
        af[1][1] = lds128<S * 32768 + 1 * 2048 + 1 * 1024>(ao);
#pragma unroll
        for (int nh = 0; nh < 2; nh++) {
            uint4 bf[4];
            if (nh == 0) {
                bf[0] = lds128<S * 32768 + 0 * 1024>(bo);
                bf[1] = lds128<S * 32768 + 1 * 1024>(bo);
                bf[2] = lds128<S * 32768 + 2 * 1024>(bo);
                bf[3] = lds128<S * 32768 + 3 * 1024>(bo);
            } else {
                bf[0] = lds128<S * 32768 + 4 * 1024>(bo);
                bf[1] = lds128<S * 32768 + 5 * 1024>(bo);
                bf[2] = lds128<S * 32768 + 6 * 1024>(bo);
                bf[3] = lds128<S * 32768 + 7 * 1024>(bo);
            }
            // 8 independent MMAs between successive writes to one acc; per-acc
            // k-order (x/y then z/w per half) identical to prior rounds.
#pragma unroll
            for (int mi = 0; mi < 2; mi++)
#pragma unroll
                for (int nj = 0; nj < 4; nj++)
                    MMA8(acc[mi][nh * 4 + nj], af[mi][0].x, af[mi][1].x,
                         af[mi][0].y, af[mi][1].y, bf[nj].x, bf[nj].y);
#pragma unroll
            for (int mi = 0; mi < 2; mi++)
#pragma unroll
                for (int nj = 0; nj < 4; nj++)
                    MMA8(acc[mi][nh * 4 + nj], af[mi][0].z, af[mi][1].z,
                         af[mi][0].w, af[mi][1].w, bf[nj].z, bf[nj].w);
        }
    }
}

// ---------------------------------------------------------------------------
// tf32 mma.sync GEMM: C[M,N] = epilogue(A[M,K] @ B^T + bias)
// B is K-major [N][K]. CTA tile 128x128, BK=32, 256 threads / 8 warps with
// 32x64 warp tiles. 2-stage cp.async double buffer, main loop unrolled x2 so
// the stage index is compile-time -> all smem addresses are base-reg+imm.
// Requires NC = K/32 even (true for K in {256,512,1024,4096}).
// MODE 1: C = tf32(relu(v + bias[n]))
// MODE 2: C = tf32(gates[m][z] * relu(v + bias[n]))
// MODE 3: C = v + sum_e gates[m][e] * eb3[e][n]   (bias carries eb3 flat 8x256)
// ---------------------------------------------------------------------------
template <int MODE>
__global__ __launch_bounds__(256, 2)
void mm_tf32(const float* __restrict__ A, const float* __restrict__ Bw,
             const float* __restrict__ bias, float* __restrict__ C,
             int K, int LDA, int LDC,
             long aStrE, long bStrE, long cStrE, int biasStrE,
             const float* __restrict__ gates)
{
    extern __shared__ char smem[];                 // 2 * (16KB A + 16KB B)
    __shared__ float bias_s[MODE == 3 ? 2048 : 128];

    const int tid  = threadIdx.x;
    const int lane = tid & 31;
    const int warp = tid >> 5;
    const int z = blockIdx.z;
    A    += (size_t)z * aStrE;
    Bw   += (size_t)z * bStrE;
    C    += (size_t)z * cStrE;
    bias += (size_t)z * biasStrE;
    const int m0 = blockIdx.y * 128;
    const int n0 = blockIdx.x * 128;

    if (MODE == 3) {
        for (int i = tid; i < 2048; i += 256) bias_s[i] = bias[i];
    } else {
        if (tid < 128) bias_s[tid] = bias[n0 + tid];
    }

    const uint32_t sb = (uint32_t)__cvta_generic_to_shared(smem);
    const int NC = K >> 5;

    // ---- loader precompute (256 threads: row r = tid>>1, 4 chunks each) ----
    const uint32_t lr  = tid >> 1;
    const uint32_t lch = (tid & 1) * 4;
    const uint32_t lfp = fperm(lr);
    uint32_t sA[4];
#pragma unroll
    for (int c = 0; c < 4; c++)
        sA[c] = sb + lr * 128 + (((lch + c) ^ lfp) << 4);
    const float* gA = A + (size_t)(m0 + lr) * LDA + lch * 4;
    const float* gB = Bw + (size_t)(n0 + lr) * K + lch * 4;

    // ---- fragment address precompute (4 registers total) ----
    const int wm = (warp & 3) * 32;       // 4 m-groups of 32 rows
    const int wn = (warp >> 2) * 64;      // 2 n-groups of 64 cols
    const int gr = lane >> 2;
    const int gc = lane & 3;
    const uint32_t aoff0 = sb + ((((uint32_t)(wm + gr)) * 8 +
                                  ((uint32_t)gc ^ fperm(wm + gr))) << 4);
    const uint32_t boff0 = sb + 16384 + ((((uint32_t)(wn + gr)) * 8 +
                                  ((uint32_t)gc ^ fperm(wn + gr))) << 4);
    const uint32_t aoff1 = aoff0 ^ 64;    // k-half p=1: chunk index ^4
    const uint32_t boff1 = boff0 ^ 64;

    float acc[2][8][4];
#pragma unroll
    for (int mi = 0; mi < 2; mi++)
#pragma unroll
        for (int ni = 0; ni < 8; ni++)
#pragma unroll
            for (int t = 0; t < 4; t++) acc[mi][ni][t] = 0.0f;

    // ---- prologue: load chunk 0 into stage 0 ----
#pragma unroll
    for (int c = 0; c < 4; c++) {
        cpa16(sA[c],  gA + c * 4);
        cpa16b(sA[c], gB + c * 4);
    }
    asm volatile("cp.async.commit_group;" ::: "memory");
    gA += 32; gB += 32;

    // ---- main loop: 2 chunks per iteration, compile-time stages ----
    for (int i = 0; i < NC; i += 2) {
        // chunk i (stage 0); load chunk i+1 into stage 1
        asm volatile("cp.async.wait_group 0;" ::: "memory");
        __syncthreads();
#pragma unroll
        for (int c = 0; c < 4; c++) {
            cpa16(sA[c] + 32768,  gA + c * 4);
            cpa16b(sA[c] + 32768, gB + c * 4);
        }
        asm volatile("cp.async.commit_group;" ::: "memory");
        gA += 32; gB += 32;
        chunk_mma<0>(acc, aoff0, aoff1, boff0, boff1);

        // chunk i+1 (stage 1); load chunk i+2 into stage 0 (if any)
        asm volatile("cp.async.wait_group 0;" ::: "memory");
        __syncthreads();
        if (i + 2 < NC) {
#pragma unroll
            for (int c = 0; c < 4; c++) {
                cpa16(sA[c],  gA + c * 4);
                cpa16b(sA[c], gB + c * 4);
            }
            asm volatile("cp.async.commit_group;" ::: "memory");
            gA += 32; gB += 32;
        }
        chunk_mma<1>(acc, aoff0, aoff1, boff0, boff1);
    }

    // ---- epilogue ----
#pragma unroll
    for (int mi = 0; mi < 2; mi++) {
        const int r0 = m0 + wm + mi * 16 + gr;
        const int r1 = r0 + 8;
        float gv0 = 0.f, gv1 = 0.f;
        float g8a[8], g8b[8];
        if (MODE == 2) {
            gv0 = gates[(size_t)r0 * 8 + z];
            gv1 = gates[(size_t)r1 * 8 + z];
        }
        if (MODE == 3) {
#pragma unroll
            for (int e = 0; e < 8; e++) {
                g8a[e] = gates[(size_t)r0 * 8 + e];
                g8b[e] = gates[(size_t)r1 * 8 + e];
            }
        }
#pragma unroll
        for (int ni = 0; ni < 8; ni++) {
            const int col  = wn + ni * 8 + 2 * gc;   // local column in [0,128)
            const int gcol = n0 + col;
            float v[4];
#pragma unroll
            for (int t = 0; t < 4; t++) v[t] = acc[mi][ni][t];

            if (MODE == 3) {
#pragma unroll
                for (int e = 0; e < 8; e++) {
                    const float b0 = bias_s[e * 256 + gcol];
                    const float b1 = bias_s[e * 256 + gcol + 1];
                    v[0] = fmaf(g8a[e], b0, v[0]);
                    v[1] = fmaf(g8a[e], b1, v[1]);
                    v[2] = fmaf(g8b[e], b0, v[2]);
                    v[3] = fmaf(g8b[e], b1, v[3]);
                }
            } else {
                v[0] = fmaxf(v[0] + bias_s[col],     0.f);
                v[1] = fmaxf(v[1] + bias_s[col + 1], 0.f);
                v[2] = fmaxf(v[2] + bias_s[col],     0.f);
                v[3] = fmaxf(v[3] + bias_s[col + 1], 0.f);
                if (MODE == 2) { v[0] *= gv0; v[1] *= gv0; v[2] *= gv1; v[3] *= gv1; }
                v[0] = tf32r(v[0]); v[1] = tf32r(v[1]);
                v[2] = tf32r(v[2]); v[3] = tf32r(v[3]);
            }
            *reinterpret_cast<float2*>(&C[(size_t)r0 * LDC + gcol]) = make_float2(v[0], v[1]);
            *reinterpret_cast<float2*>(&C[(size_t)r1 * LDC + gcol]) = make_float2(v[2], v[3]);
        }
    }
}

// ---------------------------------------------------------------------------
// Prep kernels
// ---------------------------------------------------------------------------
__global__ void k_round4(const float4* __restrict__ in, float4* __restrict__ out, int n4) {
    const int i = blockIdx.x * 256 + threadIdx.x;
    if (i < n4) {
        float4 v = in[i];
        v.x = tf32r(v.x); v.y = tf32r(v.y); v.z = tf32r(v.z); v.w = tf32r(v.w);
        out[i] = v;
    }
}

// out[b*LDO + a] = tf32(in[a*Bdim + b]); z-batched
__global__ void k_transpose_r(const float* __restrict__ in, float* __restrict__ out,
                              int Adim, int Bdim, int LDO, long inStrE, long outStrE) {
    __shared__ float t[32][33];
    in  += (size_t)blockIdx.z * inStrE;
    out += (size_t)blockIdx.z * outStrE;
    const int a0 = blockIdx.y * 32, b0 = blockIdx.x * 32;
    const int x = threadIdx.x, y = threadIdx.y;
    for (int yy = y; yy < 32; yy += 8) {
        const int a = a0 + yy, b = b0 + x;
        t[yy][x] = (a < Adim && b < Bdim) ? in[(size_t)a * Bdim + b] : 0.f;
    }
    __syncthreads();
    for (int yy = y; yy < 32; yy += 8) {
        const int b = b0 + yy, a = a0 + x;
        if (b < Bdim && a < Adim) out[(size_t)b * LDO + a] = tf32r(t[x][yy]);
    }
}

// ---------------------------------------------------------------------------
// Gating final layer + softmax (fp32, one warp per token)
// ---------------------------------------------------------------------------
__global__ void gate_softmax_kernel(const float* __restrict__ g2,
                                    const float* __restrict__ gw3,
                                    const float* __restrict__ gb3,
                                    float* __restrict__ gates)
{
    __shared__ float ws[128 * 8];
    __shared__ float bs[8];
    const int tid = threadIdx.x;
    for (int i = tid; i < 128 * 8; i += 256) ws[i] = gw3[i];
    if (tid < 8) bs[tid] = gb3[tid];
    __syncthreads();

    const int warp = tid >> 5, lane = tid & 31;
    const int token = blockIdx.x * 8 + warp;
    const float* xr = g2 + (size_t)token * 128;
    float acc[E_NUM];
#pragma unroll
    for (int e = 0; e < E_NUM; e++) acc[e] = 0.0f;
#pragma unroll
    for (int q = 0; q < 4; q++) {
        const int k = lane + 32 * q;
        const float xv = xr[k];
#pragma unroll
        for (int e = 0; e < E_NUM; e++) acc[e] = fmaf(xv, ws[k * E_NUM + e], acc[e]);
    }
#pragma unroll
    for (int e = 0; e < E_NUM; e++)
#pragma unroll
        for (int off = 16; off > 0; off >>= 1)
            acc[e] += __shfl_xor_sync(0xffffffffu, acc[e], off);
    if (lane == 0) {
        float mx = -1e30f;
#pragma unroll
        for (int e = 0; e < E_NUM; e++) { acc[e] += bs[e]; mx = fmaxf(mx, acc[e]); }
        float s = 0.0f;
#pragma unroll
        for (int e = 0; e < E_NUM; e++) { acc[e] = expf(acc[e] - mx); s += acc[e]; }
        const float inv = 1.0f / s;
        float* gp = gates + (size_t)token * E_NUM;
#pragma unroll
        for (int e = 0; e < E_NUM; e++) gp[e] = acc[e] * inv;
    }
}

// ---------------------------------------------------------------------------
extern "C" void kernel_launch(void* const* d_in, const int* in_sizes, int n_in,
                              void* d_out, int out_size)
{
    const float* x   = (const float*)d_in[0];
    const float* gw1 = (const float*)d_in[1];
    const float* gb1 = (const float*)d_in[2];
    const float* gw2 = (const float*)d_in[3];
    const float* gb2 = (const float*)d_in[4];
    const float* gw3 = (const float*)d_in[5];
    const float* gb3 = (const float*)d_in[6];
    const float* ew1 = (const float*)d_in[7];
    const float* eb1 = (const float*)d_in[8];
    const float* ew2 = (const float*)d_in[9];
    const float* eb2 = (const float*)d_in[10];
    const float* ew3 = (const float*)d_in[11];
    const float* eb3 = (const float*)d_in[12];
    float* out = (float*)d_out;

    float *xr, *gw1t, *gw2t, *w1cat, *w2t, *w3cat, *g1, *g2, *gates, *h1s, *h2s;
    cudaGetSymbolAddress((void**)&xr, g_xr);
    cudaGetSymbolAddress((void**)&gw1t, g_gw1t);
    cudaGetSymbolAddress((void**)&gw2t, g_gw2t);
    cudaGetSymbolAddress((void**)&w1cat, g_w1cat);
    cudaGetSymbolAddress((void**)&w2t, g_w2t);
    cudaGetSymbolAddress((void**)&w3cat, g_w3cat);
    cudaGetSymbolAddress((void**)&g1, g_g1);
    cudaGetSymbolAddress((void**)&g2, g_g2);
    cudaGetSymbolAddress((void**)&gates, g_gates);
    cudaGetSymbolAddress((void**)&h1s, g_h1s);
    cudaGetSymbolAddress((void**)&h2s, g_h2s);

    const int SMB = 2 * 32768;  // 65536 B dynamic smem (2-stage double buffer)
    cudaFuncSetAttribute(mm_tf32<1>, cudaFuncAttributeMaxDynamicSharedMemorySize, SMB);
    cudaFuncSetAttribute(mm_tf32<2>, cudaFuncAttributeMaxDynamicSharedMemorySize, SMB);
    cudaFuncSetAttribute(mm_tf32<3>, cudaFuncAttributeMaxDynamicSharedMemorySize, SMB);

    dim3 tpb(32, 8);
    // The profiler captures the 4th launch — keep the L1 expert GEMM there.
    k_round4<<<(B_TOK * D_IN / 4 + 255) / 256, 256>>>((const float4*)x, (float4*)xr,
                                                      B_TOK * D_IN / 4);                    // 1
    k_transpose_r<<<dim3(512 / 32, 1024 / 32, 8), tpb>>>(ew1, w1cat, 1024, 512, 1024,
                                                         1024L * 512, 512L * 1024);         // 2
    k_transpose_r<<<dim3(128 / 32, 256 / 32, 1), tpb>>>(gw2, gw2t, 256, 128, 256, 0, 0);    // 3

    // L1: [16384,1024] @ [1024->4096] -> h1s (relu+bias, tf32-rounded)          // 4 (profiled)
    mm_tf32<1><<<dim3(32, 128), 256, SMB>>>(xr, w1cat, eb1, h1s, 1024, 1024, 4096,
                                            0, 0, 0, 0, nullptr);

    k_transpose_r<<<dim3(256 / 32, 1024 / 32, 1), tpb>>>(gw1, gw1t, 1024, 256, 1024, 0, 0); // 5
    k_transpose_r<<<dim3(512 / 32, 512 / 32, 8), tpb>>>(ew2, w2t, 512, 512, 512,
                                                        512L * 512, 512L * 512);            // 6
    k_transpose_r<<<dim3(256 / 32, 512 / 32, 8), tpb>>>(ew3, w3cat, 512, 256, 4096,
                                                        512L * 256, 512);                   // 7

    // ---- gating ----
    mm_tf32<1><<<dim3(2, 128), 256, SMB>>>(xr, gw1t, gb1, g1, 1024, 1024, 256,
                                           0, 0, 0, 0, nullptr);
    mm_tf32<1><<<dim3(1, 128), 256, SMB>>>(g1, gw2t, gb2, g2, 256, 256, 128,
                                           0, 0, 0, 0, nullptr);
    gate_softmax_kernel<<<B_TOK / 8, 256>>>(g2, gw3, gb3, gates);

    // ---- experts (cont.) ----
    // L2: per-expert [16384,512]@[512,512] -> h2s (gate * relu, tf32-rounded)
    mm_tf32<2><<<dim3(4, 128, 8), 256, SMB>>>(h1s, w2t, eb2, h2s, 512, 4096, 4096,
                                              512, 512L * 512, 512, 512, gates);
    // L3: [16384,4096] @ [4096,256] -> out (+ gate-weighted eb3)
    mm_tf32<3><<<dim3(2, 128), 256, SMB>>>(h2s, w3cat, eb3, out, 4096, 4096, 256,
                                           0, 0, 0, 0, gates);
}

// round 14
// speedup vs baseline: 1.0272x; 1.0272x over previous
#include <cuda_runtime.h>
#include <math.h>
#include <stdint.h>

#define B_TOK 16384
#define D_IN  1024
#define H_DIM 512
#define O_DIM 256
#define E_NUM 8
#define N1CAT 4352   // 8*512 expert columns + 256 gating columns

// ---------------------------------------------------------------------------
// Scratch (__device__ globals; no allocation allowed)
// ---------------------------------------------------------------------------
__device__ float g_xr[(size_t)B_TOK * D_IN];            // x, tf32-rounded
__device__ float g_w1cat[(size_t)N1CAT * 1024];         // [e*512+h | 4096+g][d]
__device__ float g_b1cat[N1CAT];                        // eb1 flat + gb1
__device__ float g_gw2t[128 * 256];
__device__ float g_w2t[(size_t)E_NUM * 512 * 512];      // per-e [h_out][h_in]
__device__ float g_w3cat[(size_t)256 * 4096];           // [o][e*512+h]
__device__ float g_g2[(size_t)B_TOK * 128];
__device__ float g_gates[(size_t)B_TOK * 8];
__device__ float g_h1s[(size_t)B_TOK * N1CAT];          // experts | gating g1
__device__ float g_h2s[(size_t)B_TOK * 4096];

// ---------------------------------------------------------------------------
// Helpers
// ---------------------------------------------------------------------------
__device__ __forceinline__ float tf32r(float x) {
    float y;
    asm("cvt.rna.tf32.f32 %0, %1;" : "=f"(y) : "f"(x));
    return y;
}
__device__ __forceinline__ void cpa16(uint32_t d, const void* s) {
    asm volatile("cp.async.cg.shared.global [%0], [%1], 16;" :: "r"(d), "l"(s));
}
// Same as cpa16 but destination +16384 (B tile), folded as PTX immediate.
__device__ __forceinline__ void cpa16b(uint32_t d, const void* s) {
    asm volatile("cp.async.cg.shared.global [%0+16384], [%1], 16;" :: "r"(d), "l"(s));
}
// LDS.128 with compile-time immediate offset (stage/tile/fragment offsets).
template <int IMM>
__device__ __forceinline__ uint4 lds128(uint32_t addr) {
    uint4 v;
    asm volatile("ld.shared.v4.u32 {%0,%1,%2,%3}, [%4+%5];"
                 : "=r"(v.x), "=r"(v.y), "=r"(v.z), "=r"(v.w)
                 : "r"(addr), "n"(IMM));
    return v;
}
// Per-row 16B-chunk permutation: bijective on low-3 row bits; rows r and r+1
// differ in bit2 so adjacent rows in one LDS.128 phase hit disjoint bank
// groups. fperm(r+8) == fperm(r): fragment addresses for all row-steps
// (multiples of 8) share one register + compile-time immediates.
__device__ __forceinline__ uint32_t fperm(uint32_t r) {
    return ((r & 1u) << 2) | ((r >> 1) & 3u);
}

#define MMA8(c, a0, a1, a2, a3, b0, b1)                                         \
    asm volatile(                                                               \
        "mma.sync.aligned.m16n8k8.row.col.f32.tf32.tf32.f32 "                   \
        "{%0,%1,%2,%3}, {%4,%5,%6,%7}, {%8,%9}, {%0,%1,%2,%3};"                 \
        : "+f"((c)[0]), "+f"((c)[1]), "+f"((c)[2]), "+f"((c)[3])                \
        : "r"(a0), "r"(a1), "r"(a2), "r"(a3), "r"(b0), "r"(b1))

// One 32-k chunk of MMAs for stage S (exact R11 structure — best measured).
template <int S>
__device__ __forceinline__ void chunk_mma(float acc[2][8][4],
                                          uint32_t aoff0, uint32_t aoff1,
                                          uint32_t boff0, uint32_t boff1)
{
#pragma unroll
    for (int p = 0; p < 2; p++) {
        const uint32_t ao = p ? aoff1 : aoff0;
        const uint32_t bo = p ? boff1 : boff0;
        uint4 af[2][2];
        af[0][0] = lds128<S * 32768 + 0 * 2048 + 0 * 1024>(ao);
        af[0][1] = lds128<S * 32768 + 0 * 2048 + 1 * 1024>(ao);
        af[1][0] = lds128<S * 32768 + 1 * 2048 + 0 * 1024>(ao);
        af[1][1] = lds128<S * 32768 + 1 * 2048 + 1 * 1024>(ao);
        uint4 bf[8];
        bf[0] = lds128<S * 32768 + 0 * 1024>(bo);
        bf[1] = lds128<S * 32768 + 1 * 1024>(bo);
        bf[2] = lds128<S * 32768 + 2 * 1024>(bo);
        bf[3] = lds128<S * 32768 + 3 * 1024>(bo);
        bf[4] = lds128<S * 32768 + 4 * 1024>(bo);
        bf[5] = lds128<S * 32768 + 5 * 1024>(bo);
        bf[6] = lds128<S * 32768 + 6 * 1024>(bo);
        bf[7] = lds128<S * 32768 + 7 * 1024>(bo);
#pragma unroll
        for (int mi = 0; mi < 2; mi++)
#pragma unroll
            for (int ni = 0; ni < 8; ni++)
                MMA8(acc[mi][ni], af[mi][0].x, af[mi][1].x, af[mi][0].y,
                     af[mi][1].y, bf[ni].x, bf[ni].y);
#pragma unroll
        for (int mi = 0; mi < 2; mi++)
#pragma unroll
            for (int ni = 0; ni < 8; ni++)
                MMA8(acc[mi][ni], af[mi][0].z, af[mi][1].z, af[mi][0].w,
                     af[mi][1].w, bf[ni].z, bf[ni].w);
    }
}

// ---------------------------------------------------------------------------
// tf32 mma.sync GEMM (exact R11 core): C[M,N] = epilogue(A[M,K] @ B^T + bias)
// B is K-major [N][K]. CTA tile 128x128, BK=32, 256 threads / 8 warps with
// 32x64 warp tiles. 2-stage cp.async double buffer, main loop unrolled x2 so
// the stage index is compile-time -> all smem addresses are base-reg+imm.
// Requires NC = K/32 even.
// MODE 1: C = tf32(relu(v + bias[n]))
// MODE 2: C = tf32(gates[m][z] * relu(v + bias[n]))
// MODE 3: C = v + sum_e gates[m][e] * eb3[e][n]   (bias carries eb3 flat 8x256)
// ---------------------------------------------------------------------------
template <int MODE>
__global__ __launch_bounds__(256, 2)
void mm_tf32(const float* __restrict__ A, const float* __restrict__ Bw,
             const float* __restrict__ bias, float* __restrict__ C,
             int K, int LDA, int LDC,
             long aStrE, long bStrE, long cStrE, int biasStrE,
             const float* __restrict__ gates)
{
    extern __shared__ char smem[];                 // 2 * (16KB A + 16KB B)
    __shared__ float bias_s[MODE == 3 ? 2048 : 128];

    const int tid  = threadIdx.x;
    const int lane = tid & 31;
    const int warp = tid >> 5;
    const int z = blockIdx.z;
    A    += (size_t)z * aStrE;
    Bw   += (size_t)z * bStrE;
    C    += (size_t)z * cStrE;
    bias += (size_t)z * biasStrE;
    const int m0 = blockIdx.y * 128;
    const int n0 = blockIdx.x * 128;

    if (MODE == 3) {
        for (int i = tid; i < 2048; i += 256) bias_s[i] = bias[i];
    } else {
        if (tid < 128) bias_s[tid] = bias[n0 + tid];
    }

    const uint32_t sb = (uint32_t)__cvta_generic_to_shared(smem);
    const int NC = K >> 5;

    // ---- loader precompute (256 threads: row r = tid>>1, 4 chunks each) ----
    const uint32_t lr  = tid >> 1;
    const uint32_t lch = (tid & 1) * 4;
    const uint32_t lfp = fperm(lr);
    uint32_t sA[4];
#pragma unroll
    for (int c = 0; c < 4; c++)
        sA[c] = sb + lr * 128 + (((lch + c) ^ lfp) << 4);
    const float* gA = A + (size_t)(m0 + lr) * LDA + lch * 4;
    const float* gB = Bw + (size_t)(n0 + lr) * K + lch * 4;

    // ---- fragment address precompute (4 registers total) ----
    const int wm = (warp & 3) * 32;       // 4 m-groups of 32 rows
    const int wn = (warp >> 2) * 64;      // 2 n-groups of 64 cols
    const int gr = lane >> 2;
    const int gc = lane & 3;
    const uint32_t aoff0 = sb + ((((uint32_t)(wm + gr)) * 8 +
                                  ((uint32_t)gc ^ fperm(wm + gr))) << 4);
    const uint32_t boff0 = sb + 16384 + ((((uint32_t)(wn + gr)) * 8 +
                                  ((uint32_t)gc ^ fperm(wn + gr))) << 4);
    const uint32_t aoff1 = aoff0 ^ 64;    // k-half p=1: chunk index ^4
    const uint32_t boff1 = boff0 ^ 64;

    float acc[2][8][4];
#pragma unroll
    for (int mi = 0; mi < 2; mi++)
#pragma unroll
        for (int ni = 0; ni < 8; ni++)
#pragma unroll
            for (int t = 0; t < 4; t++) acc[mi][ni][t] = 0.0f;

    // ---- prologue: load chunk 0 into stage 0 ----
#pragma unroll
    for (int c = 0; c < 4; c++) {
        cpa16(sA[c],  gA + c * 4);
        cpa16b(sA[c], gB + c * 4);
    }
    asm volatile("cp.async.commit_group;" ::: "memory");
    gA += 32; gB += 32;

    // ---- main loop: 2 chunks per iteration, compile-time stages ----
    for (int i = 0; i < NC; i += 2) {
        asm volatile("cp.async.wait_group 0;" ::: "memory");
        __syncthreads();
#pragma unroll
        for (int c = 0; c < 4; c++) {
            cpa16(sA[c] + 32768,  gA + c * 4);
            cpa16b(sA[c] + 32768, gB + c * 4);
        }
        asm volatile("cp.async.commit_group;" ::: "memory");
        gA += 32; gB += 32;
        chunk_mma<0>(acc, aoff0, aoff1, boff0, boff1);

        asm volatile("cp.async.wait_group 0;" ::: "memory");
        __syncthreads();
        if (i + 2 < NC) {
#pragma unroll
            for (int c = 0; c < 4; c++) {
                cpa16(sA[c],  gA + c * 4);
                cpa16b(sA[c], gB + c * 4);
            }
            asm volatile("cp.async.commit_group;" ::: "memory");
            gA += 32; gB += 32;
        }
        chunk_mma<1>(acc, aoff0, aoff1, boff0, boff1);
    }

    // ---- epilogue ----
#pragma unroll
    for (int mi = 0; mi < 2; mi++) {
        const int r0 = m0 + wm + mi * 16 + gr;
        const int r1 = r0 + 8;
        float gv0 = 0.f, gv1 = 0.f;
        float g8a[8], g8b[8];
        if (MODE == 2) {
            gv0 = gates[(size_t)r0 * 8 + z];
            gv1 = gates[(size_t)r1 * 8 + z];
        }
        if (MODE == 3) {
#pragma unroll
            for (int e = 0; e < 8; e++) {
                g8a[e] = gates[(size_t)r0 * 8 + e];
                g8b[e] = gates[(size_t)r1 * 8 + e];
            }
        }
#pragma unroll
        for (int ni = 0; ni < 8; ni++) {
            const int col  = wn + ni * 8 + 2 * gc;   // local column in [0,128)
            const int gcol = n0 + col;
            float v[4];
#pragma unroll
            for (int t = 0; t < 4; t++) v[t] = acc[mi][ni][t];

            if (MODE == 3) {
#pragma unroll
                for (int e = 0; e < 8; e++) {
                    const float b0 = bias_s[e * 256 + gcol];
                    const float b1 = bias_s[e * 256 + gcol + 1];
                    v[0] = fmaf(g8a[e], b0, v[0]);
                    v[1] = fmaf(g8a[e], b1, v[1]);
                    v[2] = fmaf(g8b[e], b0, v[2]);
                    v[3] = fmaf(g8b[e], b1, v[3]);
                }
            } else {
                v[0] = fmaxf(v[0] + bias_s[col],     0.f);
                v[1] = fmaxf(v[1] + bias_s[col + 1], 0.f);
                v[2] = fmaxf(v[2] + bias_s[col],     0.f);
                v[3] = fmaxf(v[3] + bias_s[col + 1], 0.f);
                if (MODE == 2) { v[0] *= gv0; v[1] *= gv0; v[2] *= gv1; v[3] *= gv1; }
                v[0] = tf32r(v[0]); v[1] = tf32r(v[1]);
                v[2] = tf32r(v[2]); v[3] = tf32r(v[3]);
            }
            *reinterpret_cast<float2*>(&C[(size_t)r0 * LDC + gcol]) = make_float2(v[0], v[1]);
            *reinterpret_cast<float2*>(&C[(size_t)r1 * LDC + gcol]) = make_float2(v[2], v[3]);
        }
    }
}

// ---------------------------------------------------------------------------
// Prep kernels
// ---------------------------------------------------------------------------
// Rounds x to tf32 AND builds the concatenated L1 bias (eb1 | gb1) in the
// tail blocks — keeps the launch count unchanged so the profiled slot stays
// on the mega-L1 GEMM.
__global__ void k_round4_bias(const float4* __restrict__ in, float4* __restrict__ out,
                              int n4, const float* __restrict__ eb1,
                              const float* __restrict__ gb1, float* __restrict__ b1cat) {
    const int i = blockIdx.x * 256 + threadIdx.x;
    if (i < n4) {
        float4 v = in[i];
        v.x = tf32r(v.x); v.y = tf32r(v.y); v.z = tf32r(v.z); v.w = tf32r(v.w);
        out[i] = v;
    }
    const int j = i - n4;
    if (j >= 0 && j < N1CAT) b1cat[j] = (j < 4096) ? eb1[j] : gb1[j - 4096];
}

// out[b*LDO + a] = tf32(in[a*Bdim + b]); z-batched
__global__ void k_transpose_r(const float* __restrict__ in, float* __restrict__ out,
                              int Adim, int Bdim, int LDO, long inStrE, long outStrE) {
    __shared__ float t[32][33];
    in  += (size_t)blockIdx.z * inStrE;
    out += (size_t)blockIdx.z * outStrE;
    const int a0 = blockIdx.y * 32, b0 = blockIdx.x * 32;
    const int x = threadIdx.x, y = threadIdx.y;
    for (int yy = y; yy < 32; yy += 8) {
        const int a = a0 + yy, b = b0 + x;
        t[yy][x] = (a < Adim && b < Bdim) ? in[(size_t)a * Bdim + b] : 0.f;
    }
    __syncthreads();
    for (int yy = y; yy < 32; yy += 8) {
        const int b = b0 + yy, a = a0 + x;
        if (b < Bdim && a < Adim) out[(size_t)b * LDO + a] = tf32r(t[x][yy]);
    }
}

// ---------------------------------------------------------------------------
// Gating final layer + softmax (fp32, one warp per token)
// ---------------------------------------------------------------------------
__global__ void gate_softmax_kernel(const float* __restrict__ g2,
                                    const float* __restrict__ gw3,
                                    const float* __restrict__ gb3,
                                    float* __restrict__ gates)
{
    __shared__ float ws[128 * 8];
    __shared__ float bs[8];
    const int tid = threadIdx.x;
    for (int i = tid; i < 128 * 8; i += 256) ws[i] = gw3[i];
    if (tid < 8) bs[tid] = gb3[tid];
    __syncthreads();

    const int warp = tid >> 5, lane = tid & 31;
    const int token = blockIdx.x * 8 + warp;
    const float* xr = g2 + (size_t)token * 128;
    float acc[E_NUM];
#pragma unroll
    for (int e = 0; e < E_NUM; e++) acc[e] = 0.0f;
#pragma unroll
    for (int q = 0; q < 4; q++) {
        const int k = lane + 32 * q;
        const float xv = xr[k];
#pragma unroll
        for (int e = 0; e < E_NUM; e++) acc[e] = fmaf(xv, ws[k * E_NUM + e], acc[e]);
    }
#pragma unroll
    for (int e = 0; e < E_NUM; e++)
#pragma unroll
        for (int off = 16; off > 0; off >>= 1)
            acc[e] += __shfl_xor_sync(0xffffffffu, acc[e], off);
    if (lane == 0) {
        float mx = -1e30f;
#pragma unroll
        for (int e = 0; e < E_NUM; e++) { acc[e] += bs[e]; mx = fmaxf(mx, acc[e]); }
        float s = 0.0f;
#pragma unroll
        for (int e = 0; e < E_NUM; e++) { acc[e] = expf(acc[e] - mx); s += acc[e]; }
        const float inv = 1.0f / s;
        float* gp = gates + (size_t)token * E_NUM;
#pragma unroll
        for (int e = 0; e < E_NUM; e++) gp[e] = acc[e] * inv;
    }
}

// ---------------------------------------------------------------------------
extern "C" void kernel_launch(void* const* d_in, const int* in_sizes, int n_in,
                              void* d_out, int out_size)
{
    const float* x   = (const float*)d_in[0];
    const float* gw1 = (const float*)d_in[1];
    const float* gb1 = (const float*)d_in[2];
    const float* gw2 = (const float*)d_in[3];
    const float* gb2 = (const float*)d_in[4];
    const float* gw3 = (const float*)d_in[5];
    const float* gb3 = (const float*)d_in[6];
    const float* ew1 = (const float*)d_in[7];
    const float* eb1 = (const float*)d_in[8];
    const float* ew2 = (const float*)d_in[9];
    const float* eb2 = (const float*)d_in[10];
    const float* ew3 = (const float*)d_in[11];
    const float* eb3 = (const float*)d_in[12];
    float* out = (float*)d_out;

    float *xr, *w1cat, *b1cat, *gw2t, *w2t, *w3cat, *g2, *gates, *h1s, *h2s;
    cudaGetSymbolAddress((void**)&xr, g_xr);
    cudaGetSymbolAddress((void**)&w1cat, g_w1cat);
    cudaGetSymbolAddress((void**)&b1cat, g_b1cat);
    cudaGetSymbolAddress((void**)&gw2t, g_gw2t);
    cudaGetSymbolAddress((void**)&w2t, g_w2t);
    cudaGetSymbolAddress((void**)&w3cat, g_w3cat);
    cudaGetSymbolAddress((void**)&g2, g_g2);
    cudaGetSymbolAddress((void**)&gates, g_gates);
    cudaGetSymbolAddress((void**)&h1s, g_h1s);
    cudaGetSymbolAddress((void**)&h2s, g_h2s);

    const int SMB = 2 * 32768;  // 65536 B dynamic smem (2-stage double buffer)
    cudaFuncSetAttribute(mm_tf32<1>, cudaFuncAttributeMaxDynamicSharedMemorySize, SMB);
    cudaFuncSetAttribute(mm_tf32<2>, cudaFuncAttributeMaxDynamicSharedMemorySize, SMB);
    cudaFuncSetAttribute(mm_tf32<3>, cudaFuncAttributeMaxDynamicSharedMemorySize, SMB);

    dim3 tpb(32, 8);
    const int n4 = B_TOK * D_IN / 4;
    // The profiler captures the 4th launch — keep the mega-L1 GEMM there.
    k_round4_bias<<<(n4 + N1CAT + 255) / 256, 256>>>((const float4*)x, (float4*)xr,
                                                     n4, eb1, gb1, b1cat);                  // 1
    k_transpose_r<<<dim3(512 / 32, 1024 / 32, 8), tpb>>>(ew1, w1cat, 1024, 512, 1024,
                                                         1024L * 512, 512L * 1024);         // 2
    k_transpose_r<<<dim3(256 / 32, 1024 / 32, 1), tpb>>>(gw1, w1cat + (size_t)4096 * 1024,
                                                         1024, 256, 1024, 0, 0);            // 3

    // Mega-L1: [16384,1024] @ [1024 -> 4352] = experts L1 (cols 0..4095) +
    // gating L1 (cols 4096..4351), both relu+bias, tf32-rounded.             // 4 (profiled)
    mm_tf32<1><<<dim3(N1CAT / 128, 128), 256, SMB>>>(xr, w1cat, b1cat, h1s,
                                                     1024, 1024, N1CAT,
                                                     0, 0, 0, 0, nullptr);

    k_transpose_r<<<dim3(128 / 32, 256 / 32, 1), tpb>>>(gw2, gw2t, 256, 128, 256, 0, 0);    // 5
    k_transpose_r<<<dim3(512 / 32, 512 / 32, 8), tpb>>>(ew2, w2t, 512, 512, 512,
                                                        512L * 512, 512L * 512);            // 6
    k_transpose_r<<<dim3(256 / 32, 512 / 32, 8), tpb>>>(ew3, w3cat, 512, 256, 4096,
                                                        512L * 256, 512);                   // 7

    // ---- gating (reads g1 columns straight out of h1s) ----
    mm_tf32<1><<<dim3(1, 128), 256, SMB>>>(h1s + 4096, gw2t, gb2, g2, 256, N1CAT, 128,
                                           0, 0, 0, 0, nullptr);
    gate_softmax_kernel<<<B_TOK / 8, 256>>>(g2, gw3, gb3, gates);

    // ---- experts (cont.) ----
    // L2: per-expert [16384,512]@[512,512] -> h2s (gate * relu, tf32-rounded)
    mm_tf32<2><<<dim3(4, 128, 8), 256, SMB>>>(h1s, w2t, eb2, h2s, 512, N1CAT, 4096,
                                              512, 512L * 512, 512, 512, gates);
    // L3: [16384,4096] @ [4096,256] -> out (+ gate-weighted eb3)
    mm_tf32<3><<<dim3(2, 128), 256, SMB>>>(h2s, w3cat, eb3, out, 4096, 4096, 256,
                                           0, 0, 0, 0, gates);
}

// round 15
// speedup vs baseline: 1.0358x; 1.0084x over previous
#include <cuda_runtime.h>
#include <math.h>
#include <stdint.h>

#define B_TOK 16384
#define D_IN  1024
#define H_DIM 512
#define O_DIM 256
#define E_NUM 8

// ---------------------------------------------------------------------------
// Scratch (__device__ globals; no allocation allowed)
// ---------------------------------------------------------------------------
__device__ float g_xr[(size_t)B_TOK * D_IN];            // x, tf32-rounded
__device__ float g_gw1t[256 * 1024];                    // [n][k]
__device__ float g_gw2t[128 * 256];
__device__ float g_w1cat[(size_t)E_NUM * 512 * 1024];   // [e*512+h][d]
__device__ float g_w2t[(size_t)E_NUM * 512 * 512];      // per-e [h_out][h_in]
__device__ float g_w3cat[(size_t)256 * 4096];           // [o][e*512+h]
__device__ float g_g1[(size_t)B_TOK * 256];
__device__ float g_g2[(size_t)B_TOK * 128];
__device__ float g_gates[(size_t)B_TOK * 8];
__device__ float g_h1s[(size_t)B_TOK * 4096];
__device__ float g_h2s[(size_t)B_TOK * 4096];

// ---------------------------------------------------------------------------
// Helpers
// ---------------------------------------------------------------------------
__device__ __forceinline__ float tf32r(float x) {
    float y;
    asm("cvt.rna.tf32.f32 %0, %1;" : "=f"(y) : "f"(x));
    return y;
}
__device__ __forceinline__ void cpa16(uint32_t d, const void* s) {
    asm volatile("cp.async.cg.shared.global [%0], [%1], 16;" :: "r"(d), "l"(s));
}
// Same as cpa16 but destination +16384 (B tile), folded as PTX immediate.
__device__ __forceinline__ void cpa16b(uint32_t d, const void* s) {
    asm volatile("cp.async.cg.shared.global [%0+16384], [%1], 16;" :: "r"(d), "l"(s));
}
// LDS.128 with compile-time immediate offset (stage/tile/fragment offsets).
template <int IMM>
__device__ __forceinline__ uint4 lds128(uint32_t addr) {
    uint4 v;
    asm volatile("ld.shared.v4.u32 {%0,%1,%2,%3}, [%4+%5];"
                 : "=r"(v.x), "=r"(v.y), "=r"(v.z), "=r"(v.w)
                 : "r"(addr), "n"(IMM));
    return v;
}
// Per-row 16B-chunk permutation: bijective on low-3 row bits; rows r and r+1
// differ in bit2 so adjacent rows in one LDS.128 phase hit disjoint bank
// groups. fperm(r+8) == fperm(r): fragment addresses for all row-steps
// (multiples of 8) share one register + compile-time immediates.
__device__ __forceinline__ uint32_t fperm(uint32_t r) {
    return ((r & 1u) << 2) | ((r >> 1) & 3u);
}

#define MMA8(c, a0, a1, a2, a3, b0, b1)                                         \
    asm volatile(                                                               \
        "mma.sync.aligned.m16n8k8.row.col.f32.tf32.tf32.f32 "                   \
        "{%0,%1,%2,%3}, {%4,%5,%6,%7}, {%8,%9}, {%0,%1,%2,%3};"                 \
        : "+f"((c)[0]), "+f"((c)[1]), "+f"((c)[2]), "+f"((c)[3])                \
        : "r"(a0), "r"(a1), "r"(a2), "r"(a3), "r"(b0), "r"(b1))

// One 32-k chunk of MMAs for stage S (exact R11 structure — best measured).
template <int S>
__device__ __forceinline__ void chunk_mma(float acc[2][8][4],
                                          uint32_t aoff0, uint32_t aoff1,
                                          uint32_t boff0, uint32_t boff1)
{
#pragma unroll
    for (int p = 0; p < 2; p++) {
        const uint32_t ao = p ? aoff1 : aoff0;
        const uint32_t bo = p ? boff1 : boff0;
        uint4 af[2][2];
        af[0][0] = lds128<S * 32768 + 0 * 2048 + 0 * 1024>(ao);
        af[0][1] = lds128<S * 32768 + 0 * 2048 + 1 * 1024>(ao);
        af[1][0] = lds128<S * 32768 + 1 * 2048 + 0 * 1024>(ao);
        af[1][1] = lds128<S * 32768 + 1 * 2048 + 1 * 1024>(ao);
        uint4 bf[8];
        bf[0] = lds128<S * 32768 + 0 * 1024>(bo);
        bf[1] = lds128<S * 32768 + 1 * 1024>(bo);
        bf[2] = lds128<S * 32768 + 2 * 1024>(bo);
        bf[3] = lds128<S * 32768 + 3 * 1024>(bo);
        bf[4] = lds128<S * 32768 + 4 * 1024>(bo);
        bf[5] = lds128<S * 32768 + 5 * 1024>(bo);
        bf[6] = lds128<S * 32768 + 6 * 1024>(bo);
        bf[7] = lds128<S * 32768 + 7 * 1024>(bo);
#pragma unroll
        for (int mi = 0; mi < 2; mi++)
#pragma unroll
            for (int ni = 0; ni < 8; ni++)
                MMA8(acc[mi][ni], af[mi][0].x, af[mi][1].x, af[mi][0].y,
                     af[mi][1].y, bf[ni].x, bf[ni].y);
#pragma unroll
        for (int mi = 0; mi < 2; mi++)
#pragma unroll
            for (int ni = 0; ni < 8; ni++)
                MMA8(acc[mi][ni], af[mi][0].z, af[mi][1].z, af[mi][0].w,
                     af[mi][1].w, bf[ni].z, bf[ni].w);
    }
}

// ---------------------------------------------------------------------------
// tf32 mma.sync GEMM (exact R11 core): C[M,N] = epilogue(A[M,K] @ B^T + bias)
// B is K-major [N][K]. CTA tile 128x128, BK=32, 256 threads / 8 warps with
// 32x64 warp tiles. 2-stage cp.async double buffer, main loop unrolled x2 so
// the stage index is compile-time -> all smem addresses are base-reg+imm.
// Requires NC = K/32 even.
// MODE 1: C = tf32(relu(v + bias[n]))
// MODE 2: C = tf32(gates[m][z] * relu(v + bias[n]))
// MODE 3: C = v + sum_e gates[m][e] * eb3[e][n]   (bias carries eb3 flat 8x256)
// ---------------------------------------------------------------------------
template <int MODE>
__global__ __launch_bounds__(256, 2)
void mm_tf32(const float* __restrict__ A, const float* __restrict__ Bw,
             const float* __restrict__ bias, float* __restrict__ C,
             int K, int LDA, int LDC,
             long aStrE, long bStrE, long cStrE, int biasStrE,
             const float* __restrict__ gates)
{
    extern __shared__ char smem[];                 // 2 * (16KB A + 16KB B)
    __shared__ float bias_s[MODE == 3 ? 2048 : 128];

    const int tid  = threadIdx.x;
    const int lane = tid & 31;
    const int warp = tid >> 5;
    const int z = blockIdx.z;
    A    += (size_t)z * aStrE;
    Bw   += (size_t)z * bStrE;
    C    += (size_t)z * cStrE;
    bias += (size_t)z * biasStrE;
    const int m0 = blockIdx.y * 128;
    const int n0 = blockIdx.x * 128;

    if (MODE == 3) {
        for (int i = tid; i < 2048; i += 256) bias_s[i] = bias[i];
    } else {
        if (tid < 128) bias_s[tid] = bias[n0 + tid];
    }

    const uint32_t sb = (uint32_t)__cvta_generic_to_shared(smem);
    const int NC = K >> 5;

    // ---- loader precompute (256 threads: row r = tid>>1, 4 chunks each) ----
    const uint32_t lr  = tid >> 1;
    const uint32_t lch = (tid & 1) * 4;
    const uint32_t lfp = fperm(lr);
    uint32_t sA[4];
#pragma unroll
    for (int c = 0; c < 4; c++)
        sA[c] = sb + lr * 128 + (((lch + c) ^ lfp) << 4);
    const float* gA = A + (size_t)(m0 + lr) * LDA + lch * 4;
    const float* gB = Bw + (size_t)(n0 + lr) * K + lch * 4;

    // ---- fragment address precompute (4 registers total) ----
    const int wm = (warp & 3) * 32;       // 4 m-groups of 32 rows
    const int wn = (warp >> 2) * 64;      // 2 n-groups of 64 cols
    const int gr = lane >> 2;
    const int gc = lane & 3;
    const uint32_t aoff0 = sb + ((((uint32_t)(wm + gr)) * 8 +
                                  ((uint32_t)gc ^ fperm(wm + gr))) << 4);
    const uint32_t boff0 = sb + 16384 + ((((uint32_t)(wn + gr)) * 8 +
                                  ((uint32_t)gc ^ fperm(wn + gr))) << 4);
    const uint32_t aoff1 = aoff0 ^ 64;    // k-half p=1: chunk index ^4
    const uint32_t boff1 = boff0 ^ 64;

    float acc[2][8][4];
#pragma unroll
    for (int mi = 0; mi < 2; mi++)
#pragma unroll
        for (int ni = 0; ni < 8; ni++)
#pragma unroll
            for (int t = 0; t < 4; t++) acc[mi][ni][t] = 0.0f;

    // ---- prologue: load chunk 0 into stage 0 ----
#pragma unroll
    for (int c = 0; c < 4; c++) {
        cpa16(sA[c],  gA + c * 4);
        cpa16b(sA[c], gB + c * 4);
    }
    asm volatile("cp.async.commit_group;" ::: "memory");
    gA += 32; gB += 32;

    // ---- main loop: 2 chunks per iteration, compile-time stages ----
    for (int i = 0; i < NC; i += 2) {
        asm volatile("cp.async.wait_group 0;" ::: "memory");
        __syncthreads();
#pragma unroll
        for (int c = 0; c < 4; c++) {
            cpa16(sA[c] + 32768,  gA + c * 4);
            cpa16b(sA[c] + 32768, gB + c * 4);
        }
        asm volatile("cp.async.commit_group;" ::: "memory");
        gA += 32; gB += 32;
        chunk_mma<0>(acc, aoff0, aoff1, boff0, boff1);

        asm volatile("cp.async.wait_group 0;" ::: "memory");
        __syncthreads();
        if (i + 2 < NC) {
#pragma unroll
            for (int c = 0; c < 4; c++) {
                cpa16(sA[c],  gA + c * 4);
                cpa16b(sA[c], gB + c * 4);
            }
            asm volatile("cp.async.commit_group;" ::: "memory");
            gA += 32; gB += 32;
        }
        chunk_mma<1>(acc, aoff0, aoff1, boff0, boff1);
    }

    // ---- epilogue ----
#pragma unroll
    for (int mi = 0; mi < 2; mi++) {
        const int r0 = m0 + wm + mi * 16 + gr;
        const int r1 = r0 + 8;
        float gv0 = 0.f, gv1 = 0.f;
        float g8a[8], g8b[8];
        if (MODE == 2) {
            gv0 = gates[(size_t)r0 * 8 + z];
            gv1 = gates[(size_t)r1 * 8 + z];
        }
        if (MODE == 3) {
#pragma unroll
            for (int e = 0; e < 8; e++) {
                g8a[e] = gates[(size_t)r0 * 8 + e];
                g8b[e] = gates[(size_t)r1 * 8 + e];
            }
        }
#pragma unroll
        for (int ni = 0; ni < 8; ni++) {
            const int col  = wn + ni * 8 + 2 * gc;   // local column in [0,128)
            const int gcol = n0 + col;
            float v[4];
#pragma unroll
            for (int t = 0; t < 4; t++) v[t] = acc[mi][ni][t];

            if (MODE == 3) {
#pragma unroll
                for (int e = 0; e < 8; e++) {
                    const float b0 = bias_s[e * 256 + gcol];
                    const float b1 = bias_s[e * 256 + gcol + 1];
                    v[0] = fmaf(g8a[e], b0, v[0]);
                    v[1] = fmaf(g8a[e], b1, v[1]);
                    v[2] = fmaf(g8b[e], b0, v[2]);
                    v[3] = fmaf(g8b[e], b1, v[3]);
                }
            } else {
                v[0] = fmaxf(v[0] + bias_s[col],     0.f);
                v[1] = fmaxf(v[1] + bias_s[col + 1], 0.f);
                v[2] = fmaxf(v[2] + bias_s[col],     0.f);
                v[3] = fmaxf(v[3] + bias_s[col + 1], 0.f);
                if (MODE == 2) { v[0] *= gv0; v[1] *= gv0; v[2] *= gv1; v[3] *= gv1; }
                v[0] = tf32r(v[0]); v[1] = tf32r(v[1]);
                v[2] = tf32r(v[2]); v[3] = tf32r(v[3]);
            }
            *reinterpret_cast<float2*>(&C[(size_t)r0 * LDC + gcol]) = make_float2(v[0], v[1]);
            *reinterpret_cast<float2*>(&C[(size_t)r1 * LDC + gcol]) = make_float2(v[2], v[3]);
        }
    }
}

// ---------------------------------------------------------------------------
// Prep kernels
// ---------------------------------------------------------------------------
__global__ void k_round4(const float4* __restrict__ in, float4* __restrict__ out, int n4) {
    const int i = blockIdx.x * 256 + threadIdx.x;
    if (i < n4) {
        float4 v = in[i];
        v.x = tf32r(v.x); v.y = tf32r(v.y); v.z = tf32r(v.z); v.w = tf32r(v.w);
        out[i] = v;
    }
}

// out[b*LDO + a] = tf32(in[a*Bdim + b]); z-batched (ew1 -> w1cat)
__global__ void k_transpose_r(const float* __restrict__ in, float* __restrict__ out,
                              int Adim, int Bdim, int LDO, long inStrE, long outStrE) {
    __shared__ float t[32][33];
    in  += (size_t)blockIdx.z * inStrE;
    out += (size_t)blockIdx.z * outStrE;
    const int a0 = blockIdx.y * 32, b0 = blockIdx.x * 32;
    const int x = threadIdx.x, y = threadIdx.y;
    for (int yy = y; yy < 32; yy += 8) {
        const int a = a0 + yy, b = b0 + x;
        t[yy][x] = (a < Adim && b < Bdim) ? in[(size_t)a * Bdim + b] : 0.f;
    }
    __syncthreads();
    for (int yy = y; yy < 32; yy += 8) {
        const int b = b0 + yy, a = a0 + x;
        if (b < Bdim && a < Adim) out[(size_t)b * LDO + a] = tf32r(t[x][yy]);
    }
}

// Merged transpose for all remaining weights, z-dispatched:
//   z == 0      : gw1  [1024,256]  -> gw1t  (LDO 1024)
//   z == 1      : gw2  [256,128]   -> gw2t  (LDO 256)
//   z in [2,10) : ew2[e] [512,512] -> w2t+e*512*512 (LDO 512)
//   z in [10,18): ew3[e] [512,256] -> w3cat+e*512   (LDO 4096)
// Over-sized grid planes are bounds-checked to nothing.
__global__ void k_transpose_rest(const float* __restrict__ gw1,
                                 const float* __restrict__ gw2,
                                 const float* __restrict__ ew2,
                                 const float* __restrict__ ew3,
                                 float* __restrict__ gw1t,
                                 float* __restrict__ gw2t,
                                 float* __restrict__ w2t,
                                 float* __restrict__ w3cat) {
    __shared__ float t[32][33];
    const int z = blockIdx.z;
    const float* in; float* out; int Adim, Bdim, LDO;
    if (z == 0)      { in = gw1;                      out = gw1t;                    Adim = 1024; Bdim = 256; LDO = 1024; }
    else if (z == 1) { in = gw2;                      out = gw2t;                    Adim = 256;  Bdim = 128; LDO = 256;  }
    else if (z < 10) { const int e = z - 2;  in = ew2 + (size_t)e * 512 * 512; out = w2t + (size_t)e * 512 * 512; Adim = 512; Bdim = 512; LDO = 512;  }
    else             { const int e = z - 10; in = ew3 + (size_t)e * 512 * 256; out = w3cat + (size_t)e * 512;     Adim = 512; Bdim = 256; LDO = 4096; }

    const int a0 = blockIdx.y * 32, b0 = blockIdx.x * 32;
    if (a0 >= Adim || b0 >= Bdim) return;
    const int x = threadIdx.x, y = threadIdx.y;
    for (int yy = y; yy < 32; yy += 8) {
        const int a = a0 + yy, b = b0 + x;
        t[yy][x] = (a < Adim && b < Bdim) ? in[(size_t)a * Bdim + b] : 0.f;
    }
    __syncthreads();
    for (int yy = y; yy < 32; yy += 8) {
        const int b = b0 + yy, a = a0 + x;
        if (b < Bdim && a < Adim) out[(size_t)b * LDO + a] = tf32r(t[x][yy]);
    }
}

// ---------------------------------------------------------------------------
// Gating final layer + softmax (fp32, one warp per token)
// ---------------------------------------------------------------------------
__global__ void gate_softmax_kernel(const float* __restrict__ g2,
                                    const float* __restrict__ gw3,
                                    const float* __restrict__ gb3,
                                    float* __restrict__ gates)
{
    __shared__ float ws[128 * 8];
    __shared__ float bs[8];
    const int tid = threadIdx.x;
    for (int i = tid; i < 128 * 8; i += 256) ws[i] = gw3[i];
    if (tid < 8) bs[tid] = gb3[tid];
    __syncthreads();

    const int warp = tid >> 5, lane = tid & 31;
    const int token = blockIdx.x * 8 + warp;
    const float* xr = g2 + (size_t)token * 128;
    float acc[E_NUM];
#pragma unroll
    for (int e = 0; e < E_NUM; e++) acc[e] = 0.0f;
#pragma unroll
    for (int q = 0; q < 4; q++) {
        const int k = lane + 32 * q;
        const float xv = xr[k];
#pragma unroll
        for (int e = 0; e < E_NUM; e++) acc[e] = fmaf(xv, ws[k * E_NUM + e], acc[e]);
    }
#pragma unroll
    for (int e = 0; e < E_NUM; e++)
#pragma unroll
        for (int off = 16; off > 0; off >>= 1)
            acc[e] += __shfl_xor_sync(0xffffffffu, acc[e], off);
    if (lane == 0) {
        float mx = -1e30f;
#pragma unroll
        for (int e = 0; e < E_NUM; e++) { acc[e] += bs[e]; mx = fmaxf(mx, acc[e]); }
        float s = 0.0f;
#pragma unroll
        for (int e = 0; e < E_NUM; e++) { acc[e] = expf(acc[e] - mx); s += acc[e]; }
        const float inv = 1.0f / s;
        float* gp = gates + (size_t)token * E_NUM;
#pragma unroll
        for (int e = 0; e < E_NUM; e++) gp[e] = acc[e] * inv;
    }
}

// ---------------------------------------------------------------------------
extern "C" void kernel_launch(void* const* d_in, const int* in_sizes, int n_in,
                              void* d_out, int out_size)
{
    const float* x   = (const float*)d_in[0];
    const float* gw1 = (const float*)d_in[1];
    const float* gb1 = (const float*)d_in[2];
    const float* gw2 = (const float*)d_in[3];
    const float* gb2 = (const float*)d_in[4];
    const float* gw3 = (const float*)d_in[5];
    const float* gb3 = (const float*)d_in[6];
    const float* ew1 = (const float*)d_in[7];
    const float* eb1 = (const float*)d_in[8];
    const float* ew2 = (const float*)d_in[9];
    const float* eb2 = (const float*)d_in[10];
    const float* ew3 = (const float*)d_in[11];
    const float* eb3 = (const float*)d_in[12];
    float* out = (float*)d_out;

    float *xr, *gw1t, *gw2t, *w1cat, *w2t, *w3cat, *g1, *g2, *gates, *h1s, *h2s;
    cudaGetSymbolAddress((void**)&xr, g_xr);
    cudaGetSymbolAddress((void**)&gw1t, g_gw1t);
    cudaGetSymbolAddress((void**)&gw2t, g_gw2t);
    cudaGetSymbolAddress((void**)&w1cat, g_w1cat);
    cudaGetSymbolAddress((void**)&w2t, g_w2t);
    cudaGetSymbolAddress((void**)&w3cat, g_w3cat);
    cudaGetSymbolAddress((void**)&g1, g_g1);
    cudaGetSymbolAddress((void**)&g2, g_g2);
    cudaGetSymbolAddress((void**)&gates, g_gates);
    cudaGetSymbolAddress((void**)&h1s, g_h1s);
    cudaGetSymbolAddress((void**)&h2s, g_h2s);

    const int SMB = 2 * 32768;  // 65536 B dynamic smem (2-stage double buffer)
    cudaFuncSetAttribute(mm_tf32<1>, cudaFuncAttributeMaxDynamicSharedMemorySize, SMB);
    cudaFuncSetAttribute(mm_tf32<2>, cudaFuncAttributeMaxDynamicSharedMemorySize, SMB);
    cudaFuncSetAttribute(mm_tf32<3>, cudaFuncAttributeMaxDynamicSharedMemorySize, SMB);

    dim3 tpb(32, 8);
    // The profiler captures the 4th launch — keep the L1 expert GEMM there.
    k_round4<<<(B_TOK * D_IN / 4 + 255) / 256, 256>>>((const float4*)x, (float4*)xr,
                                                      B_TOK * D_IN / 4);                    // 1
    k_transpose_r<<<dim3(512 / 32, 1024 / 32, 8), tpb>>>(ew1, w1cat, 1024, 512, 1024,
                                                         1024L * 512, 512L * 1024);         // 2
    k_transpose_rest<<<dim3(16, 32, 18), tpb>>>(gw1, gw2, ew2, ew3,
                                                gw1t, gw2t, w2t, w3cat);                    // 3

    // L1: [16384,1024] @ [1024->4096] -> h1s (relu+bias, tf32-rounded)          // 4 (profiled)
    mm_tf32<1><<<dim3(32, 128), 256, SMB>>>(xr, w1cat, eb1, h1s, 1024, 1024, 4096,
                                            0, 0, 0, 0, nullptr);

    // ---- gating ----
    mm_tf32<1><<<dim3(2, 128), 256, SMB>>>(xr, gw1t, gb1, g1, 1024, 1024, 256,
                                           0, 0, 0, 0, nullptr);
    mm_tf32<1><<<dim3(1, 128), 256, SMB>>>(g1, gw2t, gb2, g2, 256, 256, 128,
                                           0, 0, 0, 0, nullptr);
    gate_softmax_kernel<<<B_TOK / 8, 256>>>(g2, gw3, gb3, gates);

    // ---- experts (cont.) ----
    // L2: per-expert [16384,512]@[512,512] -> h2s (gate * relu, tf32-rounded)
    mm_tf32<2><<<dim3(4, 128, 8), 256, SMB>>>(h1s, w2t, eb2, h2s, 512, 4096, 4096,
                                              512, 512L * 512, 512, 512, gates);
    // L3: [16384,4096] @ [4096,256] -> out (+ gate-weighted eb3)
    mm_tf32<3><<<dim3(2, 128), 256, SMB>>>(h2s, w3cat, eb3, out, 4096, 4096, 256,
                                           0, 0, 0, 0, gates);
}